// round 10
// baseline (speedup 1.0000x reference)
#include <cuda_runtime.h>
#include <cuda_bf16.h>

// LightplaneSplatter: splat N rays x 72 samples x 16 channels into a
// (1,128,128,128,16) grid with trilinear weights, masking OOB corners.
//
// R9: slab-table corner dedup (R8) with sample-parallel phase 1 (R2 shape).
// Block = 1 ray. Thread M<128 owns a 16-slot (4x4 cross-axis) smem column of
// corner-vertex weights for dominant-axis slab M, anchored on the ray line.
// Phase 1: 4 threads per sample compute geometry once and scatter their 8
// corner weights into the table with direct-indexed smem atomicAdd (no hash).
// Phase 2: compact nonzero in-bounds vertices. Phase 3: flush each distinct
// vertex as one 64B-coalesced quad of red.global.add.v4.f32.
//
// Inputs (metadata order):
//   d_in[0] directions  float32 [N,3]
//   d_in[1] origins     float32 [N,3]
//   d_in[2] near        float32 [N]
//   d_in[3] far         float32 [N]
//   d_in[4] encoding    float32 [N,16]
//   d_in[5] grid_idx    int32   [N]
// Output: float32 grid [1,128,128,128,16] flattened (33,554,432 elems).

#define GW 128
#define GH 128
#define GD 128
#define GC 16
#define NUM_SAMPLES 64
#define NUM_SAMPLES_INF 8
#define ST (NUM_SAMPLES + NUM_SAMPLES_INF)  // 72
#define DISPARITY_AT_INF 1e-4f

#define NT 128        // slabs (dominant-axis coords)
#define NSLOT 16      // 4x4 cross-axis window per slab
#define NTHREADS 288  // 4 threads x 72 samples

__device__ __forceinline__ void red_add_v4(float* p, float x, float y, float z, float w) {
    asm volatile("red.global.add.v4.f32 [%0], {%1, %2, %3, %4};"
                 :: "l"(p), "f"(x), "f"(y), "f"(z), "f"(w)
                 : "memory");
}

__global__ void __launch_bounds__(NTHREADS) splat_kernel(
    const float* __restrict__ dirs,
    const float* __restrict__ orig,
    const float* __restrict__ nearv,
    const float* __restrict__ farv,
    const float* __restrict__ enc,
    const int*   __restrict__ gidx,
    float* __restrict__ out)
{
    __shared__ float tbl[NSLOT * NT];            // [slot][M] SoA
    __shared__ int   y0s[NT], v0s[NT];
    __shared__ unsigned short list[NT * NSLOT];  // compacted (M,slot)
    __shared__ int cnt;

    const int n   = blockIdx.x;
    const int tid = threadIdx.x;

    // ---- per-ray params (broadcast) ----
    const float d0 = dirs[n * 3 + 0], d1 = dirs[n * 3 + 1], d2 = dirs[n * 3 + 2];
    const float o0 = orig[n * 3 + 0], o1 = orig[n * 3 + 1], o2 = orig[n * 3 + 2];
    const float nr = nearv[n], fr = farv[n];
    const int   b_ = gidx[n];

    // dominant axis (uniform across block)
    const float ab0 = fabsf(d0), ab1 = fabsf(d1), ab2 = fabsf(d2);
    int a = (ab1 > ab0) ? 1 : 0;
    float am = (ab1 > ab0) ? ab1 : ab0;
    if (ab2 > am) a = 2;

    float oa, ou, ov, da, du_, dv_;
    if (a == 0)      { oa = o0; da = d0; ou = o1; du_ = d1; ov = o2; dv_ = d2; }
    else if (a == 1) { oa = o1; da = d1; ou = o2; du_ = d2; ov = o0; dv_ = d0; }
    else             { oa = o2; da = d2; ou = o0; du_ = d0; ov = o1; dv_ = d1; }

    // ray line in voxel coords
    const float ca = (oa + 1.0f) * 63.5f, ma = da * 63.5f;
    const float cu = (ou + 1.0f) * 63.5f, mu = du_ * 63.5f;
    const float cv = (ov + 1.0f) * 63.5f, mv = dv_ * 63.5f;

    // ---- init anchors + table ----
    if (tid < NT) {
        const float tM = ((float)tid - ca) / ma;
        y0s[tid] = (int)floorf(cu + mu * tM) - 1;
        v0s[tid] = (int)floorf(cv + mv * tM) - 1;
    }
    for (int i = tid; i < NSLOT * NT; i += NTHREADS) tbl[i] = 0.0f;
    if (tid == 0) cnt = 0;
    __syncthreads();

    // ---- phase 1: per-sample geometry + scatter (4 threads/sample) ----
    {
        const int si  = tid >> 2;   // 0..71
        const int sub = tid & 3;    // (du,dv) = (sub>>1, sub&1)

        float t;
        if (si < NUM_SAMPLES) {
            t = nr + (fr - nr) * (((float)si + 0.5f) * (1.0f / NUM_SAMPLES));
        } else {
            const float j    = (float)(si - NUM_SAMPLES + 1) * (1.0f / NUM_SAMPLES_INF);
            const float invf = 1.0f / fr;
            const float disp = invf + (DISPARITY_AT_INF - invf) * j;
            t = 1.0f / disp;
        }

        const float va = (oa + t * da  + 1.0f) * 0.5f * 127.0f;
        const float vu = (ou + t * du_ + 1.0f) * 0.5f * 127.0f;
        const float vv = (ov + t * dv_ + 1.0f) * 0.5f * 127.0f;

        const float baf = floorf(va);
        const float buf = floorf(vu);
        const float bvf = floorf(vv);

        // Written so NaN also fails -> skip.
        const bool maybe_in =
            (baf >= -1.0f) && (baf <= 127.0f) &&
            (buf >= -1.0f) && (buf <= 127.0f) &&
            (bvf >= -1.0f) && (bvf <= 127.0f);

        if (maybe_in) {
            const float fa = va - baf;
            const float fu = vu - buf;
            const float fv = vv - bvf;
            const int ba = (int)baf;
            const int bu = (int)buf;
            const int bv = (int)bvf;

            const int cdu = sub >> 1;
            const int cdv = sub & 1;
            const int iu  = bu + cdu;
            const int iv  = bv + cdv;
            const float wuv = (cdu ? fu : 1.0f - fu) * (cdv ? fv : 1.0f - fv);

#pragma unroll
            for (int cda = 0; cda < 2; cda++) {
                const int M = ba + cda;
                if ((unsigned)M >= (unsigned)NT) continue;  // OOB slab (masked anyway)
                const float w = wuv * (cda ? fa : 1.0f - fa);
                const int du0 = iu - y0s[M];
                const int dv0 = iv - v0s[M];
                if ((unsigned)du0 <= 3u && (unsigned)dv0 <= 3u) {
                    atomicAdd(&tbl[(du0 * 4 + dv0) * NT + M], w);
                } else if ((unsigned)iu < 128u && (unsigned)iv < 128u) {
                    // ulp-boundary fallback: direct global REDs (essentially never)
                    int ix, iy, iz;
                    if (a == 0)      { ix = M;  iy = iu; iz = iv; }
                    else if (a == 1) { iy = M;  iz = iu; ix = iv; }
                    else             { iz = M;  ix = iu; iy = iv; }
                    float* p = out + ((((long long)b_ * GD + iz) * GH + iy) * GW + ix) * GC;
#pragma unroll
                    for (int q = 0; q < 4; q++) {
                        const float4 e4 = *reinterpret_cast<const float4*>(enc + n * GC + q * 4);
                        red_add_v4(p + q * 4, w * e4.x, w * e4.y, w * e4.z, w * e4.w);
                    }
                }
            }
        }
    }
    __syncthreads();

    // ---- phase 2: compact nonzero, in-bounds vertices ----
    if (tid < NT) {
        const int M  = tid;
        const int y0 = y0s[M];
        const int v0 = v0s[M];
#pragma unroll
        for (int idx = 0; idx < NSLOT; idx++) {
            if (tbl[idx * NT + M] != 0.0f) {
                const int iu = y0 + (idx >> 2);
                const int iv = v0 + (idx & 3);
                if ((unsigned)iu < 128u && (unsigned)iv < 128u) {
                    const int pos = atomicAdd(&cnt, 1);
                    list[pos] = (unsigned short)((M << 4) | idx);
                }
            }
        }
    }
    __syncthreads();

    // ---- phase 3: flush, 4-lane quads, 64B red.v4 per vertex ----
    const int nent = cnt;
    const int c4 = tid & 3;
    const int g  = tid >> 2;  // 0..71
    const float4 e4 = *reinterpret_cast<const float4*>(enc + n * GC + c4 * 4);

    for (int i = g; i < nent; i += NTHREADS / 4) {
        const unsigned ent = list[i];
        const int Mm  = (int)(ent >> 4);
        const int idx = (int)(ent & 15u);
        const float w = tbl[idx * NT + Mm];
        const int iu = y0s[Mm] + (idx >> 2);
        const int iv = v0s[Mm] + (idx & 3);
        int ix, iy, iz;
        if (a == 0)      { ix = Mm;  iy = iu; iz = iv; }
        else if (a == 1) { iy = Mm;  iz = iu; ix = iv; }
        else             { iz = Mm;  ix = iu; iy = iv; }
        float* p = out + ((((long long)b_ * GD + iz) * GH + iy) * GW + ix) * GC + c4 * 4;
        red_add_v4(p, w * e4.x, w * e4.y, w * e4.z, w * e4.w);
    }
}

extern "C" void kernel_launch(void* const* d_in, const int* in_sizes, int n_in,
                              void* d_out, int out_size)
{
    const float* dirs  = (const float*)d_in[0];
    const float* orig  = (const float*)d_in[1];
    const float* nearv = (const float*)d_in[2];
    const float* farv  = (const float*)d_in[3];
    const float* enc   = (const float*)d_in[4];
    const int*   gidx  = (const int*)  d_in[5];
    float* out = (float*)d_out;

    const int N = in_sizes[2];  // near has one element per ray

    cudaMemsetAsync(d_out, 0, (size_t)out_size * sizeof(float));

    splat_kernel<<<N, NTHREADS>>>(dirs, orig, nearv, farv, enc, gidx, out);
}

// round 11
// speedup vs baseline: 1.2592x; 1.2592x over previous
#include <cuda_runtime.h>
#include <cuda_bf16.h>

// LightplaneSplatter: splat N rays x 72 samples x 16 channels into a
// (1,128,128,128,16) grid with trilinear weights, masking OOB corners.
//
// R10: R2 lane mapping (4 float4-lanes per sample, 8 samples per warp, one
// block per ray) + register-only neighbor merge: when consecutive samples'
// cells differ by exactly +-1 in the x field of the packed key (same y,z
// cell), the donor's 4 x-facing corner weights are shuffled into the
// receiver's coincident corners and the donor skips those 4 reductions.
// Merging runs entirely in the shuffle/ALU pipes, which are idle; the
// binding L1 RED-wavefront count drops by the pair-merge rate.
//
// Inputs (metadata order):
//   d_in[0] directions  float32 [N,3]
//   d_in[1] origins     float32 [N,3]
//   d_in[2] near        float32 [N]
//   d_in[3] far         float32 [N]
//   d_in[4] encoding    float32 [N,16]
//   d_in[5] grid_idx    int32   [N]
// Output: float32 grid [1,128,128,128,16] flattened (33,554,432 elems).

#define GW 128
#define GH 128
#define GD 128
#define GC 16
#define NUM_SAMPLES 64
#define NUM_SAMPLES_INF 8
#define ST (NUM_SAMPLES + NUM_SAMPLES_INF)  // 72
#define DISPARITY_AT_INF 1e-4f

// Strides in floats
#define SXs (GC)            // 16
#define SYs (GW * GC)       // 2048
#define SZs (GH * GW * GC)  // 262144

__device__ __forceinline__ void red_add_v4(float* p, float x, float y, float z, float w) {
    asm volatile("red.global.add.v4.f32 [%0], {%1, %2, %3, %4};"
                 :: "l"(p), "f"(x), "f"(y), "f"(z), "f"(w)
                 : "memory");
}

// block: x = 4 channel-quads (float4 each), y = 72 samples -> 288 threads
// grid:  x = N rays.  Warp w = samples 8w..8w+7; lane = c4 + 4*s_local.
__global__ void __launch_bounds__(288) splat_kernel(
    const float* __restrict__ dirs,
    const float* __restrict__ orig,
    const float* __restrict__ nearv,
    const float* __restrict__ farv,
    const float* __restrict__ enc,
    const int*   __restrict__ gidx,
    float* __restrict__ out)
{
    const unsigned FULL = 0xffffffffu;
    const int n  = blockIdx.x;
    const int si = threadIdx.y;        // 0..71
    const int c4 = threadIdx.x;        // 0..3

    const float nr = nearv[n];
    const float fr = farv[n];

    float t;
    if (si < NUM_SAMPLES) {
        t = nr + (fr - nr) * (((float)si + 0.5f) * (1.0f / NUM_SAMPLES));
    } else {
        const float j    = (float)(si - NUM_SAMPLES + 1) * (1.0f / NUM_SAMPLES_INF);
        const float invf = 1.0f / fr;
        const float disp = invf + (DISPARITY_AT_INF - invf) * j;
        t = 1.0f / disp;
    }

    const float px = orig[n * 3 + 0] + t * dirs[n * 3 + 0];
    const float py = orig[n * 3 + 1] + t * dirs[n * 3 + 1];
    const float pz = orig[n * 3 + 2] + t * dirs[n * 3 + 2];

    const float vx = (px + 1.0f) * 0.5f * (float)(GW - 1);
    const float vy = (py + 1.0f) * 0.5f * (float)(GH - 1);
    const float vz = (pz + 1.0f) * 0.5f * (float)(GD - 1);

    const float bxf = floorf(vx);
    const float byf = floorf(vy);
    const float bzf = floorf(vz);

    // Written so NaN also fails -> OOB.
    const bool inb_sample =
        (bxf >= -1.0f) && (bxf <= (float)(GW - 1)) &&
        (byf >= -1.0f) && (byf <= (float)(GH - 1)) &&
        (bzf >= -1.0f) && (bzf <= (float)(GD - 1));

    const int bx = (int)bxf;
    const int by = (int)byf;
    const int bz = (int)bzf;

    // Packed cell key; sentinel for OOB so no +-1 relation can match it.
    // Fields: z,y,x each 9 bits, values in [0,128] for valid cells.
    const int key = inb_sample
        ? ((((bz + 1) << 9) | (by + 1)) << 9) | (bx + 1)
        : -1000000;

    // Per-sample corner weights, k = dx + 2*dy + 4*dz (zero when OOB).
    float v[8];
    if (inb_sample) {
        const float fx = vx - bxf;
        const float fy = vy - byf;
        const float fz = vz - bzf;
        const float wx0 = 1.0f - fx, wx1 = fx;
        const float wy0 = 1.0f - fy, wy1 = fy;
        const float wz0 = 1.0f - fz, wz1 = fz;
        const float w00 = wx0 * wy0, w10 = wx1 * wy0;
        const float w01 = wx0 * wy1, w11 = wx1 * wy1;
        v[0] = w00 * wz0; v[1] = w10 * wz0;
        v[2] = w01 * wz0; v[3] = w11 * wz0;
        v[4] = w00 * wz1; v[5] = w10 * wz1;
        v[6] = w01 * wz1; v[7] = w11 * wz1;
    } else {
#pragma unroll
        for (int k = 0; k < 8; k++) v[k] = 0.0f;
    }

    // ---- register-only neighbor merge (all 32 lanes participate) ----
    const int prev_key = __shfl_up_sync(FULL, key, 4);   // lanes 0-3: own key
    const int next_key = __shfl_down_sync(FULL, key, 4); // lanes 28-31: own key

    float pv[8];
#pragma unroll
    for (int k = 0; k < 8; k++) pv[k] = __shfl_up_sync(FULL, v[k], 4);

    const bool valid = (key >= 0);

    // Receive: prev donated its x-facing corners coincident with ours.
    if (valid && prev_key == key - 1) {          // prev cell at x-1: its odd = my even
        v[0] += pv[1]; v[2] += pv[3]; v[4] += pv[5]; v[6] += pv[7];
    } else if (valid && prev_key == key + 1) {   // prev cell at x+1: its even = my odd
        v[1] += pv[0]; v[3] += pv[2]; v[5] += pv[4]; v[7] += pv[6];
    }

    // Donate: skip the corner parity the next sample absorbs.
    const bool skip_odd  = valid && (next_key == key + 1);  // my dx=1 = next's dx=0
    const bool skip_even = valid && (next_key == key - 1);  // my dx=0 = next's dx=1

    if (!valid) return;  // after all shuffles: safe to exit

    const int b = gidx[n];
    const float4 e = *reinterpret_cast<const float4*>(enc + n * GC + c4 * 4);

    const bool x0 = (unsigned)bx       < GW;
    const bool x1 = (unsigned)(bx + 1) < GW;
    const bool y0 = (unsigned)by       < GH;
    const bool y1 = (unsigned)(by + 1) < GH;
    const bool z0 = (unsigned)bz       < GD;
    const bool z1 = (unsigned)(bz + 1) < GD;

    const long long basef =
        ((((long long)b * GD + bz) * GH + by) * GW + bx) * GC + c4 * 4;
    float* const pb = out + basef;

#pragma unroll
    for (int k = 0; k < 8; k++) {
        const int ddx = k & 1, ddy = (k >> 1) & 1, ddz = (k >> 2) & 1;
        if (ddx ? skip_odd : skip_even) continue;
        const bool inb = (ddx ? x1 : x0) & (ddy ? y1 : y0) & (ddz ? z1 : z0);
        if (inb) {
            const float w = v[k];
            red_add_v4(pb + (ddz * SZs + ddy * SYs + ddx * SXs),
                       w * e.x, w * e.y, w * e.z, w * e.w);
        }
    }
}

extern "C" void kernel_launch(void* const* d_in, const int* in_sizes, int n_in,
                              void* d_out, int out_size)
{
    const float* dirs  = (const float*)d_in[0];
    const float* orig  = (const float*)d_in[1];
    const float* nearv = (const float*)d_in[2];
    const float* farv  = (const float*)d_in[3];
    const float* enc   = (const float*)d_in[4];
    const int*   gidx  = (const int*)  d_in[5];
    float* out = (float*)d_out;

    const int N = in_sizes[2];  // near has one element per ray

    cudaMemsetAsync(d_out, 0, (size_t)out_size * sizeof(float));

    dim3 block(4, ST, 1);   // 4 channel-quads x 72 samples = 288 threads
    dim3 grid(N, 1, 1);
    splat_kernel<<<grid, block>>>(dirs, orig, nearv, farv, enc, gidx, out);
}